// round 4
// baseline (speedup 1.0000x reference)
#include <cuda_runtime.h>
#include <math.h>
#include <stdint.h>

#define NB      16384
#define FANOUT  16
#define BE      (NB*FANOUT)
#define EMB     128
#define HID     256
#define NEDGE   16

#define BM      128
#define BN      128
#define KC      32
#define ARP     80        // A row pitch in floats (16 mod 32 banks -> conflict-free reads)

// ---- persistent scratch ----
// packed weights: per (G=k/8, c=0..3, n): float4 {hi(8G+c,n), hi(8G+c+4,n), lo(8G+c,n), lo(8G+c+4,n)}
__device__ float g_Wsrc4 [EMB*HID*2];
__device__ float g_Wdst4 [EMB*HID*2];
__device__ float g_Wself4[EMB*HID*2];
__device__ float g_W24   [HID*HID*2];
__device__ float g_Wneigh4[HID*HID*2];
__device__ float g_relb2[NEDGE*HID];
__device__ float g_neigh[(size_t)NB*HID];

// ------------------------------------------------------------------
__device__ __forceinline__ float tf32_rna(float x) {
    uint32_t r;
    asm("cvt.rna.tf32.f32 %0, %1;" : "=r"(r) : "f"(x));
    return __uint_as_float(r);
}
__device__ __forceinline__ void split2(float x, float& h, float& l) {
    h = tf32_rna(x);
    l = tf32_rna(x - h);
}
__device__ __forceinline__ void mma8(float* d, const float* a, const float* b) {
    asm volatile("mma.sync.aligned.m16n8k8.row.col.f32.tf32.tf32.f32 "
        "{%0,%1,%2,%3},{%4,%5,%6,%7},{%8,%9},{%0,%1,%2,%3};"
        : "+f"(d[0]), "+f"(d[1]), "+f"(d[2]), "+f"(d[3])
        : "r"(__float_as_uint(a[0])), "r"(__float_as_uint(a[1])),
          "r"(__float_as_uint(a[2])), "r"(__float_as_uint(a[3])),
          "r"(__float_as_uint(b[0])), "r"(__float_as_uint(b[1])));
}
template<int N> __device__ __forceinline__ void cp_wait() {
    asm volatile("cp.async.wait_group %0;" :: "n"(N));
}
__device__ __forceinline__ void cp16(void* dst, const void* src) {
    uint32_t sa = (uint32_t)__cvta_generic_to_shared(dst);
    asm volatile("cp.async.cg.shared.global [%0], [%1], 16;" :: "r"(sa), "l"(src));
}

// ------------------------------------------------------------------
// prep: pack weights into split float4 layout
// ------------------------------------------------------------------
__device__ __forceinline__ void pack_one(const float* __restrict__ W, float* out,
                                         int K, int i) {
    int G = i >> 10;            // i / (4*HID)
    int rem = i & 1023;
    int c = rem >> 8, n = rem & 255;
    int ka = G*8 + c;
    float ha, la, hb, lb;
    split2(W[n*K + ka],     ha, la);
    split2(W[n*K + ka + 4], hb, lb);
    ((float4*)out)[i] = make_float4(ha, hb, la, lb);
}
__global__ void prep_pack_all(const float* __restrict__ Wsrc, const float* __restrict__ Wdst,
                              const float* __restrict__ Wself, const float* __restrict__ W2,
                              const float* __restrict__ Wneigh) {
    int i = blockIdx.x * blockDim.x + threadIdx.x;
    if (i < EMB*HID/2) {      // 16384 float4 per EMB-K weight
        pack_one(Wsrc,  g_Wsrc4,  EMB, i);
        pack_one(Wdst,  g_Wdst4,  EMB, i);
        pack_one(Wself, g_Wself4, EMB, i);
    }
    if (i < HID*HID/2) {      // 32768 float4 per HID-K weight
        pack_one(W2,     g_W24,     HID, i);
        pack_one(Wneigh, g_Wneigh4, HID, i);
    }
}

__global__ void prep_relb2(const float* __restrict__ edge_emb,
                           const float* __restrict__ edge_lin_w,
                           const float* __restrict__ b2) {
    int n = threadIdx.x;
    for (int r = 0; r < NEDGE; r++) {
        float s = b2[n];
        #pragma unroll 4
        for (int k = 0; k < EMB; k++)
            s = fmaf(edge_emb[r*EMB + k], edge_lin_w[n*EMB + k], s);
        g_relb2[r*HID + n] = s;
    }
}

// ------------------------------------------------------------------
// producers
// ------------------------------------------------------------------
// prefetch one KC=32 weight chunk (global k-group base gg0) into B buffer via cp.async
__device__ __forceinline__ void prefetchB(float* B4, const float* W4, int gg0,
                                          int colbase, int tid) {
    #pragma unroll
    for (int j = 0; j < 8; j++) {
        int lin = j*256 + tid;         // 0..2047
        int gc  = lin >> 7;            // (g*4+c) 0..15
        int n   = lin & 127;
        int g = gc >> 2, c = gc & 3;
        const float* src = W4 + (((size_t)(gg0 + g)*4 + c)*HID + colbase + n)*4;
        float* dst = B4 + gc*512 + ((n*4) ^ (c*8));
        cp16(dst, src);
    }
    asm volatile("cp.async.commit_group;");
}

// gather+split one KC=32 A chunk: thread (m = tid>>1, half = tid&1)
__device__ __forceinline__ void stageA_vals(float* A4, const float* v, int tid) {
    int m = tid >> 1, half = tid & 1;
    float* base = A4 + m*ARP + half*32;
    #pragma unroll
    for (int gr = 0; gr < 2; gr++)
        #pragma unroll
        for (int c = 0; c < 4; c++) {
            float ha, la, hb, lb;
            split2(v[gr*8 + c],     ha, la);
            split2(v[gr*8 + c + 4], hb, lb);
            *(float4*)(base + gr*16 + c*4) = make_float4(ha, hb, la, lb);
        }
}
__device__ __forceinline__ void stageA_gather(float* A4, const float* rowPtr,
                                              int k0, int tid) {
    int half = tid & 1;
    float v[16];
    const float4* p = (const float4*)(rowPtr + k0 + half*16);
    #pragma unroll
    for (int j = 0; j < 4; j++) {
        float4 t = p[j];
        v[4*j] = t.x; v[4*j+1] = t.y; v[4*j+2] = t.z; v[4*j+3] = t.w;
    }
    stageA_vals(A4, v, tid);
}

// ------------------------------------------------------------------
// warp mma over one KC=32 chunk (packed layouts, 3xTF32)
// ------------------------------------------------------------------
__device__ __forceinline__ void mma_chunkP(const float* __restrict__ A4,
                                           const float* __restrict__ B4,
                                           float (&acc)[2][8][4],
                                           int wm, int wn, int lane) {
    int q = lane >> 2, c = lane & 3;
    #pragma unroll
    for (int g = 0; g < 4; g++) {
        float4 va[2][2];
        #pragma unroll
        for (int mf = 0; mf < 2; mf++) {
            int r = wm*32 + mf*16 + q;
            va[mf][0] = *(const float4*)(A4 + r*ARP + g*16 + c*4);
            va[mf][1] = *(const float4*)(A4 + (r+8)*ARP + g*16 + c*4);
        }
        #pragma unroll
        for (int nf = 0; nf < 8; nf++) {
            int nel = wn*64 + nf*8 + q;
            float4 vb = *(const float4*)(B4 + (g*4 + c)*512 + ((nel*4) ^ (c*8)));
            float bh[2] = { vb.x, vb.y };
            float bl[2] = { vb.z, vb.w };
            #pragma unroll
            for (int mf = 0; mf < 2; mf++) {
                float ah[4] = { va[mf][0].x, va[mf][1].x, va[mf][0].y, va[mf][1].y };
                float al[4] = { va[mf][0].z, va[mf][1].z, va[mf][0].w, va[mf][1].w };
                mma8(acc[mf][nf], ah, bh);
                mma8(acc[mf][nf], al, bh);
                mma8(acc[mf][nf], ah, bl);
            }
        }
    }
}

#define SMEM_DYN_FLOATS (BM*ARP + 2*4*4*512)   // A4 + two B buffers = 26624 floats

// ------------------------------------------------------------------
// event kernel
// ------------------------------------------------------------------
__global__ __launch_bounds__(256, 2)
void ev_kernel(const int* __restrict__ nbr_ev,
               const int* __restrict__ ev_st, const int* __restrict__ ev_dt,
               const int* __restrict__ ev_et,
               const int* __restrict__ ev_sid, const int* __restrict__ ev_did,
               const int* __restrict__ ev_ts,  const float* __restrict__ ev_w,
               const float* __restrict__ emb0, const float* __restrict__ emb1,
               const float* __restrict__ mlp_w1, const float* __restrict__ mlp_b1) {
    extern __shared__ float smem[];
    float* A4 = smem;                       // BM*ARP
    float* Bb[2] = { A4 + BM*ARP, A4 + BM*ARP + 4*4*512 };

    __shared__ int   s_src[BM], s_dst[BM];  // (id<<1)|type
    __shared__ float s_ts[BM], s_lw[BM], s_val[BM];
    __shared__ int   s_rel[BM];
    __shared__ float s_w1a[HID], s_w1b[HID], s_b1[HID];

    int tid  = threadIdx.x;
    int lane = tid & 31;
    int w    = tid >> 5;
    int wm   = w & 3, wn = w >> 2;
    int colbase = blockIdx.y * BN;

    if (tid < BM) {
        int ev = nbr_ev[blockIdx.x*BM + tid];
        int e  = ev < 0 ? 0 : ev;
        s_val[tid] = ev < 0 ? 0.f : 1.f;
        s_src[tid] = (ev_sid[e] << 1) | (ev_st[e] != 0);
        s_dst[tid] = (ev_did[e] << 1) | (ev_dt[e] != 0);
        s_rel[tid] = ev_et[e];
        s_ts[tid]  = (float)ev_ts[e] / 1000000.0f;
        s_lw[tid]  = log1pf(ev_w[e]);
    }
    s_w1a[tid] = mlp_w1[tid*2 + 0];
    s_w1b[tid] = mlp_w1[tid*2 + 1];
    s_b1[tid]  = mlp_b1[tid];

    prefetchB(Bb[0], g_Wsrc4, 0, colbase, tid);
    __syncthreads();

    float acc[2][8][4];
    #pragma unroll
    for (int a = 0; a < 2; a++)
        #pragma unroll
        for (int b = 0; b < 8; b++)
            #pragma unroll
            for (int qq = 0; qq < 4; qq++) acc[a][b][qq] = 0.f;

    int m = tid >> 1, half = tid & 1;
    int p = 0;

    #pragma unroll 1
    for (int t = 0; t < 16; t++) {
        // --- stage A for chunk t ---
        if (t < 8) {
            int id = (t < 4) ? s_src[m] : s_dst[m];
            const float* rp = (id & 1 ? emb1 : emb0) + (size_t)(id >> 1)*EMB;
            stageA_gather(A4, rp, (t & 3)*KC, tid);
        } else {
            int k0 = (t - 8)*KC;
            float ts = s_ts[m], lw = s_lw[m];
            float v[16];
            #pragma unroll
            for (int j = 0; j < 16; j++) {
                int kg = k0 + half*16 + j;
                v[j] = fmaxf(fmaf(ts, s_w1a[kg], fmaf(lw, s_w1b[kg], s_b1[kg])), 0.f);
            }
            stageA_vals(A4, v, tid);
        }
        // --- prefetch B for chunk t+1 ---
        if (t < 15) {
            int u = t + 1;
            const float* W4; int gg0;
            if (u < 4)      { W4 = g_Wsrc4; gg0 = u*4; }
            else if (u < 8) { W4 = g_Wdst4; gg0 = (u-4)*4; }
            else            { W4 = g_W24;   gg0 = (u-8)*4; }
            prefetchB(Bb[p^1], W4, gg0, colbase, tid);
            cp_wait<1>();
        } else {
            cp_wait<0>();
        }
        __syncthreads();
        mma_chunkP(A4, Bb[p], acc, wm, wn, lane);
        __syncthreads();
        p ^= 1;
    }

    // --- epilogue: + relb2, relu, mask, fanout-mean via shfl ---
    #pragma unroll
    for (int mf = 0; mf < 2; mf++) {
        int r0 = wm*32 + mf*16 + (lane >> 2);
        int r1 = r0 + 8;
        float v0 = s_val[r0], v1 = s_val[r1];
        int rel0 = s_rel[r0], rel1 = s_rel[r1];
        int brow = blockIdx.x*8 + wm*2 + mf;
        #pragma unroll
        for (int nf = 0; nf < 8; nf++) {
            int cl = wn*64 + nf*8 + 2*(lane & 3);
            int gc = colbase + cl;
            float p0 = fmaxf(acc[mf][nf][0] + g_relb2[rel0*HID + gc],     0.f)*v0
                     + fmaxf(acc[mf][nf][2] + g_relb2[rel1*HID + gc],     0.f)*v1;
            float p1 = fmaxf(acc[mf][nf][1] + g_relb2[rel0*HID + gc + 1], 0.f)*v0
                     + fmaxf(acc[mf][nf][3] + g_relb2[rel1*HID + gc + 1], 0.f)*v1;
            p0 += __shfl_xor_sync(0xffffffffu, p0, 4);
            p0 += __shfl_xor_sync(0xffffffffu, p0, 8);
            p0 += __shfl_xor_sync(0xffffffffu, p0, 16);
            p1 += __shfl_xor_sync(0xffffffffu, p1, 4);
            p1 += __shfl_xor_sync(0xffffffffu, p1, 8);
            p1 += __shfl_xor_sync(0xffffffffu, p1, 16);
            if ((lane >> 2) == 0) {
                *(float2*)&g_neigh[(size_t)brow*HID + gc] =
                    make_float2(p0 * 0.0625f, p1 * 0.0625f);
            }
        }
    }
}

// ------------------------------------------------------------------
// output kernel
// ------------------------------------------------------------------
__global__ __launch_bounds__(256, 2)
void out_kernel(const int* __restrict__ node_ids,
                const float* __restrict__ emb0,
                float* __restrict__ out) {
    extern __shared__ float smem[];
    float* A4 = smem;
    float* Bb[2] = { A4 + BM*ARP, A4 + BM*ARP + 4*4*512 };

    __shared__ int s_id[BM];

    int tid  = threadIdx.x;
    int lane = tid & 31;
    int w    = tid >> 5;
    int wm   = w & 3, wn = w >> 2;
    int colbase = blockIdx.y * BN;
    int rowbase = blockIdx.x * BM;

    if (tid < BM) s_id[tid] = node_ids[rowbase + tid];

    prefetchB(Bb[0], g_Wself4, 0, colbase, tid);
    __syncthreads();

    float acc[2][8][4];
    #pragma unroll
    for (int a = 0; a < 2; a++)
        #pragma unroll
        for (int b = 0; b < 8; b++)
            #pragma unroll
            for (int qq = 0; qq < 4; qq++) acc[a][b][qq] = 0.f;

    int m = tid >> 1;
    int p = 0;

    #pragma unroll 1
    for (int t = 0; t < 12; t++) {
        if (t < 4) {
            const float* rp = emb0 + (size_t)s_id[m]*EMB;
            stageA_gather(A4, rp, t*KC, tid);
        } else {
            const float* rp = g_neigh + (size_t)(rowbase + m)*HID;
            stageA_gather(A4, rp, (t-4)*KC, tid);
        }
        if (t < 11) {
            int u = t + 1;
            const float* W4; int gg0;
            if (u < 4) { W4 = g_Wself4;  gg0 = u*4; }
            else       { W4 = g_Wneigh4; gg0 = (u-4)*4; }
            prefetchB(Bb[p^1], W4, gg0, colbase, tid);
            cp_wait<1>();
        } else {
            cp_wait<0>();
        }
        __syncthreads();
        mma_chunkP(A4, Bb[p], acc, wm, wn, lane);
        __syncthreads();
        p ^= 1;
    }

    #pragma unroll
    for (int mf = 0; mf < 2; mf++) {
        int r0 = rowbase + wm*32 + mf*16 + (lane >> 2);
        int r1 = r0 + 8;
        #pragma unroll
        for (int nf = 0; nf < 8; nf++) {
            int gc = colbase + wn*64 + nf*8 + 2*(lane & 3);
            *(float2*)&out[(size_t)r0*HID + gc] =
                make_float2(fmaxf(acc[mf][nf][0], 0.f), fmaxf(acc[mf][nf][1], 0.f));
            *(float2*)&out[(size_t)r1*HID + gc] =
                make_float2(fmaxf(acc[mf][nf][2], 0.f), fmaxf(acc[mf][nf][3], 0.f));
        }
    }
}

// ------------------------------------------------------------------
extern "C" void kernel_launch(void* const* d_in, const int* in_sizes, int n_in,
                              void* d_out, int out_size) {
    const int*   node_ids = (const int*)d_in[0];
    const int*   nbr_ev   = (const int*)d_in[1];
    const int*   ev_st    = (const int*)d_in[2];
    const int*   ev_dt    = (const int*)d_in[3];
    const int*   ev_et    = (const int*)d_in[4];
    const int*   ev_sid   = (const int*)d_in[5];
    const int*   ev_did   = (const int*)d_in[6];
    const int*   ev_ts    = (const int*)d_in[7];
    const float* ev_w     = (const float*)d_in[8];
    const float* emb0     = (const float*)d_in[9];
    const float* emb1     = (const float*)d_in[10];
    const float* edge_emb = (const float*)d_in[11];
    const float* edge_lin = (const float*)d_in[12];
    const float* mlp_w1   = (const float*)d_in[13];
    const float* mlp_b1   = (const float*)d_in[14];
    const float* mlp_w2   = (const float*)d_in[15];
    const float* mlp_b2   = (const float*)d_in[16];
    const float* wsrc     = (const float*)d_in[17];
    const float* wdst     = (const float*)d_in[18];
    const float* wself    = (const float*)d_in[19];
    const float* wneigh   = (const float*)d_in[20];
    float* out = (float*)d_out;

    size_t smem_dyn = (size_t)SMEM_DYN_FLOATS * sizeof(float);
    cudaFuncSetAttribute(ev_kernel,  cudaFuncAttributeMaxDynamicSharedMemorySize, (int)smem_dyn);
    cudaFuncSetAttribute(out_kernel, cudaFuncAttributeMaxDynamicSharedMemorySize, (int)smem_dyn);

    prep_pack_all<<<(HID*HID/2 + 255)/256, 256>>>(wsrc, wdst, wself, mlp_w2, wneigh);
    prep_relb2<<<1, 256>>>(edge_emb, edge_lin, mlp_b2);

    dim3 gev(BE/BM, 2);
    ev_kernel<<<gev, 256, smem_dyn>>>(nbr_ev, ev_st, ev_dt, ev_et, ev_sid, ev_did,
                                      ev_ts, ev_w, emb0, emb1, mlp_w1, mlp_b1);
    dim3 gout(NB/BM, 2);
    out_kernel<<<gout, 256, smem_dyn>>>(node_ids, emb0, out);
}